// round 3
// baseline (speedup 1.0000x reference)
#include <cuda_runtime.h>
#include <cuda_bf16.h>
#include <cstdint>

// Problem constants (from reference):
//   N_NODES = 12288, N_EDGES = 393216, LATENT = 128, EDGE_F = 4
// Inputs (metadata order):
//   d_in[0] = z          float32 [12288, 128]
//   d_in[1] = edge_index int64-or-int32 [2, 393216]  (JAX silently downcasts
//             jnp.int64 -> int32 when x64 is disabled; detect at runtime)
//   d_in[2] = edge_attr  float32 [393216, 4]
//   d_in[3] = W          float32 [1, 256]
//   d_in[4] = b          float32 [1]
// Output: float32 [12288, 12288]

#define N_NODES 12288
#define N_EDGES 393216

// Scratch: per-cell winning edge id (last-wins via atomicMax).
__device__ int g_winner[(size_t)N_NODES * N_NODES];
// 1 if edge_index buffer holds int64, 0 if int32.
__device__ int g_idx64;

// ---------------------------------------------------------------------------
// Kernel 0: detect edge_index dtype. For int64 data, odd int32 words are the
// high halves of small non-negative indices => all zero. For int32 data they
// are random indices in [0, 12288) — P(all 128 zero) ~ 0.
// ---------------------------------------------------------------------------
__global__ void detect_dtype_kernel(const int* __restrict__ ei32) {
    if (threadIdx.x == 0 && blockIdx.x == 0) {
        int any = 0;
        #pragma unroll
        for (int i = 1; i < 256; i += 2) any |= ei32[i];
        g_idx64 = (any == 0) ? 1 : 0;
    }
}

// Fetch index #pos from the edge_index buffer under either dtype.
__device__ __forceinline__ long long load_idx(const void* ei, size_t pos, int is64) {
    if (is64) return ((const long long*)ei)[pos];
    return (long long)((const int*)ei)[pos];
}

// ---------------------------------------------------------------------------
// Kernel 1: zero the dense output — pure HBM-write bound (~604 MB).
// ---------------------------------------------------------------------------
__global__ void zero_out_kernel(float4* __restrict__ out, size_t n4) {
    size_t i = (size_t)blockIdx.x * blockDim.x + threadIdx.x;
    size_t stride = (size_t)gridDim.x * blockDim.x;
    float4 zero = make_float4(0.f, 0.f, 0.f, 0.f);
    for (; i < n4; i += stride) out[i] = zero;
}

// ---------------------------------------------------------------------------
// Kernel 2: reset winner slots ONLY at touched cells (E random 4B writes).
// ---------------------------------------------------------------------------
__global__ void reset_winner_kernel(const void* __restrict__ ei) {
    int e = blockIdx.x * blockDim.x + threadIdx.x;
    if (e >= N_EDGES) return;
    int is64 = g_idx64;
    long long r = load_idx(ei, e, is64);
    long long c = load_idx(ei, (size_t)N_EDGES + e, is64);
    if ((unsigned long long)r >= N_NODES || (unsigned long long)c >= N_NODES) return;
    g_winner[(size_t)r * N_NODES + c] = -1;
}

// ---------------------------------------------------------------------------
// Kernel 3: scatter-add summed edge_attr; record last-wins edge id.
// ---------------------------------------------------------------------------
__global__ void scatter_attr_kernel(const void* __restrict__ ei,
                                    const float4* __restrict__ attr,
                                    float* __restrict__ out) {
    int e = blockIdx.x * blockDim.x + threadIdx.x;
    if (e >= N_EDGES) return;
    int is64 = g_idx64;
    long long r = load_idx(ei, e, is64);
    long long c = load_idx(ei, (size_t)N_EDGES + e, is64);
    if ((unsigned long long)r >= N_NODES || (unsigned long long)c >= N_NODES) return;
    float4 a = attr[e];
    size_t cell = (size_t)r * N_NODES + c;
    atomicAdd(&out[cell], a.x + a.y + a.z + a.w);
    atomicMax(&g_winner[cell], e);  // last occurrence (max edge id) wins ".set"
}

// ---------------------------------------------------------------------------
// Kernel 4: warp-per-edge probe:
//   prob = dot(z[r], W[0:128]) + dot(z[c], W[128:256]) + b
// Only the winning edge for a cell adds its prob (overwrite semantics of .set).
// z is 6 MB -> L2-resident; each warp reads 2x512B coalesced.
// ---------------------------------------------------------------------------
__global__ void prob_kernel(const float* __restrict__ z,
                            const void* __restrict__ ei,
                            const float* __restrict__ W,
                            const float* __restrict__ b,
                            float* __restrict__ out) {
    int gwarp = (blockIdx.x * blockDim.x + threadIdx.x) >> 5;
    int lane  = threadIdx.x & 31;
    if (gwarp >= N_EDGES) return;
    int is64 = g_idx64;

    long long r = load_idx(ei, gwarp, is64);
    long long c = load_idx(ei, (size_t)N_EDGES + gwarp, is64);
    if ((unsigned long long)r >= N_NODES || (unsigned long long)c >= N_NODES) return;

    // 32 lanes x float4 = 128 floats per row (coalesced 512B)
    float4 zr = reinterpret_cast<const float4*>(z + (size_t)r * 128)[lane];
    float4 zc = reinterpret_cast<const float4*>(z + (size_t)c * 128)[lane];
    float4 w1 = reinterpret_cast<const float4*>(W)[lane];
    float4 w2 = reinterpret_cast<const float4*>(W + 128)[lane];

    float s = zr.x * w1.x + zr.y * w1.y + zr.z * w1.z + zr.w * w1.w
            + zc.x * w2.x + zc.y * w2.y + zc.z * w2.z + zc.w * w2.w;

    #pragma unroll
    for (int o = 16; o > 0; o >>= 1)
        s += __shfl_xor_sync(0xFFFFFFFFu, s, o);

    if (lane == 0) {
        size_t cell = (size_t)r * N_NODES + c;
        if (g_winner[cell] == gwarp) {
            // unique winner per cell -> plain RMW is race-free here
            out[cell] += s + b[0];
        }
    }
}

// ---------------------------------------------------------------------------
extern "C" void kernel_launch(void* const* d_in, const int* in_sizes, int n_in,
                              void* d_out, int out_size) {
    const float* z    = (const float*)d_in[0];
    const void*  ei   = d_in[1];
    const float4* attr = (const float4*)d_in[2];
    const float* W    = (const float*)d_in[3];
    const float* b    = (const float*)d_in[4];
    float*       out  = (float*)d_out;

    // 0) detect edge_index dtype (int64 vs silently-downcast int32)
    detect_dtype_kernel<<<1, 32>>>((const int*)ei);

    // 1) zero output (size from harness, not assumption)
    size_t n4 = (size_t)out_size / 4;
    zero_out_kernel<<<148 * 32, 256>>>((float4*)out, n4);

    // 2) reset winner at touched cells
    reset_winner_kernel<<<(N_EDGES + 255) / 256, 256>>>(ei);

    // 3) scatter-add attr sums + record winners
    scatter_attr_kernel<<<(N_EDGES + 255) / 256, 256>>>(ei, attr, out);

    // 4) warp-per-edge probe + winner-gated add
    int threads = 256;                                     // 8 warps / block
    int blocks  = (N_EDGES * 32 + threads - 1) / threads;  // 49152 blocks
    prob_kernel<<<blocks, threads>>>(z, ei, W, b, out);
}

// round 4
// speedup vs baseline: 1.7116x; 1.7116x over previous
#include <cuda_runtime.h>
#include <cuda_bf16.h>
#include <cstdint>

// Inputs (metadata order):
//   d_in[0] = z          float32 [12288, 128]
//   d_in[1] = edge_index int32 [2, 393216] (jnp.int64 silently downcast; detect)
//   d_in[2] = edge_attr  float32 [393216, 4]
//   d_in[3] = W          float32 [1, 256]
//   d_in[4] = b          float32 [1]
// Output: float32 [12288, 12288]
//
// out[r,c] = sum_dup(attr_sum) + (u[r] + v[c] + b) added ONCE per distinct cell
// (duplicate edges share (r,c) => identical prob => first-touch wins == set).

#define N_NODES 12288
#define N_EDGES 393216

#define RESET_BLOCKS 1536   // 1536*256 = 393216 threads, one per edge
#define UV_BLOCKS    1536   // 1536*8 warps = 12288, one warp per node
#define ZERO_BLOCKS  4736   // 148 SMs * 32

// first-touch flag per cell (0 = untouched this launch)
__device__ int g_winner[(size_t)N_NODES * N_NODES];
// per-node partial dots: u[i] = dot(z[i], W[0:128]) + b, v[i] = dot(z[i], W[128:256])
__device__ float g_u[N_NODES];
__device__ float g_v[N_NODES];

// ---------------------------------------------------------------------------
// In-block edge_index dtype detect: if data is int64, the odd int32 words are
// high halves of small non-negative indices => all zero. For int32 data they
// are random indices in [0,12288) — P(64 all zero) ~ 0. Warp-0 ballot.
// Returns 1 for int64, 0 for int32 (uniform across block via shared).
// ---------------------------------------------------------------------------
__device__ __forceinline__ int block_detect_is64(const int* __restrict__ ei32,
                                                 int* sh_flag) {
    if (threadIdx.x < 32) {
        int w = ei32[2 * threadIdx.x + 1];
        unsigned any = __ballot_sync(0xFFFFFFFFu, w != 0);
        if (threadIdx.x == 0) *sh_flag = (any == 0u) ? 1 : 0;
    }
    __syncthreads();
    return *sh_flag;
}

__device__ __forceinline__ long long load_idx(const void* ei, size_t pos, int is64) {
    if (is64) return ((const long long*)ei)[pos];
    return (long long)((const int*)ei)[pos];
}

// ---------------------------------------------------------------------------
// Kernel A: fused prep. All writes are mutually independent:
//   blocks [0, RESET)            : winner[touched cell] = 0
//   blocks [RESET, RESET+UV)     : u[node], v[node] (warp-per-node dot)
//   blocks [RESET+UV, ...)       : zero out (grid-stride float4)
// Reset/UV first so their latency hides under the 604MB streaming zero.
// ---------------------------------------------------------------------------
__global__ void prep_kernel(float4* __restrict__ out, size_t n4,
                            const void* __restrict__ ei,
                            const float* __restrict__ z,
                            const float* __restrict__ W,
                            const float* __restrict__ b) {
    __shared__ int sh_flag;
    int bid = blockIdx.x;

    if (bid < RESET_BLOCKS) {
        int is64 = block_detect_is64((const int*)ei, &sh_flag);
        int e = bid * 256 + threadIdx.x;
        if (e >= N_EDGES) return;
        long long r = load_idx(ei, e, is64);
        long long c = load_idx(ei, (size_t)N_EDGES + e, is64);
        if ((unsigned long long)r >= N_NODES || (unsigned long long)c >= N_NODES) return;
        g_winner[(size_t)r * N_NODES + c] = 0;
    } else if (bid < RESET_BLOCKS + UV_BLOCKS) {
        int node = (bid - RESET_BLOCKS) * 8 + (threadIdx.x >> 5);
        int lane = threadIdx.x & 31;
        if (node >= N_NODES) return;
        float4 zv = reinterpret_cast<const float4*>(z + (size_t)node * 128)[lane];
        float4 w1 = reinterpret_cast<const float4*>(W)[lane];
        float4 w2 = reinterpret_cast<const float4*>(W + 128)[lane];
        float s1 = zv.x * w1.x + zv.y * w1.y + zv.z * w1.z + zv.w * w1.w;
        float s2 = zv.x * w2.x + zv.y * w2.y + zv.z * w2.z + zv.w * w2.w;
        #pragma unroll
        for (int o = 16; o > 0; o >>= 1) {
            s1 += __shfl_xor_sync(0xFFFFFFFFu, s1, o);
            s2 += __shfl_xor_sync(0xFFFFFFFFu, s2, o);
        }
        if (lane == 0) {
            g_u[node] = s1 + b[0];   // fold bias into u
            g_v[node] = s2;
        }
    } else {
        size_t i = (size_t)(bid - RESET_BLOCKS - UV_BLOCKS) * blockDim.x + threadIdx.x;
        size_t stride = (size_t)ZERO_BLOCKS * blockDim.x;
        float4 zero = make_float4(0.f, 0.f, 0.f, 0.f);
        for (; i < n4; i += stride) out[i] = zero;
    }
}

// ---------------------------------------------------------------------------
// Kernel B: fused edge scatter. Thread-per-edge:
//   p = u[r] + v[c]            (96KB tables, L1/L2 hot)
//   first = (atomicExch(&winner[cell], 1) == 0)
//   atomicAdd(&out[cell], attr_sum + (first ? p : 0))
// ---------------------------------------------------------------------------
__global__ void edge_kernel(const void* __restrict__ ei,
                            const float4* __restrict__ attr,
                            float* __restrict__ out) {
    __shared__ int sh_flag;
    int is64 = block_detect_is64((const int*)ei, &sh_flag);

    int e = blockIdx.x * 256 + threadIdx.x;
    if (e >= N_EDGES) return;
    long long r = load_idx(ei, e, is64);
    long long c = load_idx(ei, (size_t)N_EDGES + e, is64);
    if ((unsigned long long)r >= N_NODES || (unsigned long long)c >= N_NODES) return;

    float4 a = attr[e];
    size_t cell = (size_t)r * N_NODES + c;
    float p = g_u[r] + g_v[c];

    int old = atomicExch(&g_winner[cell], 1);
    float add = a.x + a.y + a.z + a.w + (old == 0 ? p : 0.0f);
    atomicAdd(&out[cell], add);
}

// ---------------------------------------------------------------------------
extern "C" void kernel_launch(void* const* d_in, const int* in_sizes, int n_in,
                              void* d_out, int out_size) {
    const float*  z    = (const float*)d_in[0];
    const void*   ei   = d_in[1];
    const float4* attr = (const float4*)d_in[2];
    const float*  W    = (const float*)d_in[3];
    const float*  b    = (const float*)d_in[4];
    float*        out  = (float*)d_out;

    size_t n4 = (size_t)out_size / 4;

    prep_kernel<<<RESET_BLOCKS + UV_BLOCKS + ZERO_BLOCKS, 256>>>(
        (float4*)out, n4, ei, z, W, b);

    edge_kernel<<<(N_EDGES + 255) / 256, 256>>>(ei, attr, out);
}